// round 9
// baseline (speedup 1.0000x reference)
#include <cuda_runtime.h>
#include <math.h>
#include <cstdint>

#define B_   4
#define N_   2048
#define D_   512
#define H_   8
#define DH   64
#define DQ2  128          // concatenated head dim: [q | q_met]
#define BHn  (B_*H_)      // 32
#define ROWS (B_*N_)      // 8192
#define SCALE 0.125f      // 64^-0.5

// Scratch (device globals — no allocations allowed)
__device__ float g_Q2[BHn * N_ * DQ2];  // 32 MB  [(bh), n, 128]  (tf32-rounded)
__device__ float g_K2[BHn * N_ * DQ2];  // 32 MB                  (tf32-rounded)
__device__ float g_Vt[BHn * DH * N_];   // 16 MB  [(bh), d, n]    (tf32-rounded, transposed)
__device__ float g_OH[ROWS * D_];       // 16 MB  (b, n, h*64+d)
__device__ float g_RS[BHn * N_];        // 256 KB  1/rowsum

// ===========================================================================
// helpers
// ===========================================================================
__device__ __forceinline__ float tf32r(float x) {
    uint32_t u = __float_as_uint(x);
    asm("cvt.rn.tf32.f32 %0, %1;" : "=r"(u) : "r"(u));
    return __uint_as_float(u);
}
__device__ __forceinline__ void mma8(float c[4], const uint32_t a[4], const uint32_t b[2]) {
    asm volatile(
        "mma.sync.aligned.m16n8k8.row.col.f32.tf32.tf32.f32 "
        "{%0,%1,%2,%3}, {%4,%5,%6,%7}, {%8,%9}, {%0,%1,%2,%3};"
        : "+f"(c[0]), "+f"(c[1]), "+f"(c[2]), "+f"(c[3])
        : "r"(a[0]), "r"(a[1]), "r"(a[2]), "r"(a[3]), "r"(b[0]), "r"(b[1]));
}

// ===========================================================================
// Kernel 1: proj via mma.sync tf32 (R5 verbatim).
// ===========================================================================
#define APAD 44
#define BPAD 136
#define PROJ_SMEM ((2*128*APAD + 2*32*BPAD) * 4)   // 79872 B

__global__ __launch_bounds__(256) void proj_mma(
    const float* __restrict__ x, const float* __restrict__ met,
    const float* __restrict__ yz, const float* __restrict__ Wq,
    const float* __restrict__ Wk, const float* __restrict__ Wv)
{
    extern __shared__ float smf[];
    float* As = smf;                    // 2 x [128][APAD]
    float* Bs = smf + 2*128*APAD;       // 2 x [32][BPAD]

    const int mode = blockIdx.z;
    const float* A = (mode == 0) ? x : (mode == 1 || mode == 3) ? met : yz;
    const float* W = (mode < 2) ? Wq : (mode < 4) ? Wk : Wv;

    const int tid = threadIdx.x, lane = tid & 31, wid = tid >> 5;
    const int wm = wid >> 1, wn = wid & 1;
    const int row0 = blockIdx.y * 128;
    const int col0 = blockIdx.x * 128;

    float4 ta[4]; float tb[16];
    auto loadA = [&](int k0) {
        #pragma unroll
        for (int q = 0; q < 4; q++) {
            int e = tid + q * 256;
            int r = e >> 3, kg = e & 7;
            ta[q] = *(const float4*)&A[(long)(row0 + r) * D_ + k0 + kg * 4];
        }
    };
    auto loadB = [&](int k0) {
        #pragma unroll
        for (int j = 0; j < 16; j++) {
            int i = tid + j * 256;
            int k = i >> 7, n = i & 127;
            tb[j] = W[(long)(k0 + k) * D_ + col0 + n];
        }
    };
    auto stsA = [&](int buf) {
        float* Ab = As + buf * 128 * APAD;
        #pragma unroll
        for (int q = 0; q < 4; q++) {
            int e = tid + q * 256;
            int r = e >> 3, kg = e & 7;
            float4 v = ta[q];
            v.x = tf32r(v.x); v.y = tf32r(v.y); v.z = tf32r(v.z); v.w = tf32r(v.w);
            *(float4*)&Ab[r * APAD + kg * 4] = v;
        }
    };
    auto stsB = [&](int buf) {
        float* Bb = Bs + buf * 32 * BPAD;
        #pragma unroll
        for (int j = 0; j < 16; j++) {
            int i = tid + j * 256;
            int k = i >> 7, n = i & 127;
            Bb[k * BPAD + n] = tf32r(tb[j]);
        }
    };

    float acc[2][8][4] = {};
    loadA(0); loadB(0); stsA(0); stsB(0);
    __syncthreads();

    for (int c = 0; c < 16; c++) {
        if (c + 1 < 16) { loadA((c + 1) * 32); loadB((c + 1) * 32); }
        const int buf = c & 1;
        const float* Ab = As + buf * 128 * APAD;
        const float* Bb = Bs + buf * 32 * BPAD;

        #pragma unroll
        for (int ks = 0; ks < 4; ks++) {
            const int kk = ks * 8 + (lane & 3);
            uint32_t a[2][4], b[8][2];
            #pragma unroll
            for (int ma = 0; ma < 2; ma++) {
                int r = wm * 32 + ma * 16 + (lane >> 2);
                a[ma][0] = __float_as_uint(Ab[r * APAD + kk]);
                a[ma][1] = __float_as_uint(Ab[(r + 8) * APAD + kk]);
                a[ma][2] = __float_as_uint(Ab[r * APAD + kk + 4]);
                a[ma][3] = __float_as_uint(Ab[(r + 8) * APAD + kk + 4]);
            }
            #pragma unroll
            for (int na = 0; na < 8; na++) {
                int n = wn * 64 + na * 8 + (lane >> 2);
                b[na][0] = __float_as_uint(Bb[kk * BPAD + n]);
                b[na][1] = __float_as_uint(Bb[(kk + 4) * BPAD + n]);
            }
            #pragma unroll
            for (int ma = 0; ma < 2; ma++)
                #pragma unroll
                for (int na = 0; na < 8; na++)
                    mma8(acc[ma][na], a[ma], b[na]);
        }
        __syncthreads();
        if (c + 1 < 16) { stsA(buf ^ 1); stsB(buf ^ 1); }
        __syncthreads();
    }

    #pragma unroll
    for (int ma = 0; ma < 2; ma++) {
        #pragma unroll
        for (int half = 0; half < 2; half++) {
            int r = row0 + wm * 32 + ma * 16 + half * 8 + (lane >> 2);
            int bb = r >> 11, n = r & 2047;
            #pragma unroll
            for (int na = 0; na < 8; na++) {
                int cgl = col0 + wn * 64 + na * 8 + (lane & 3) * 2;
                int h = cgl >> 6, d = cgl & 63;
                float p = tf32r(acc[ma][na][half * 2 + 0]);
                float q = tf32r(acc[ma][na][half * 2 + 1]);
                long base = (long)(bb * H_ + h) * N_ + n;
                if (mode == 0)
                    *(float2*)&g_Q2[base * DQ2 + d] = make_float2(p, q);
                else if (mode == 1)
                    *(float2*)&g_Q2[base * DQ2 + d + DH] = make_float2(p, q);
                else if (mode == 2)
                    *(float2*)&g_K2[base * DQ2 + d] = make_float2(p, q);
                else if (mode == 3)
                    *(float2*)&g_K2[base * DQ2 + d + DH] = make_float2(p, q);
                else {
                    g_Vt[((long)(bb * H_ + h) * DH + d) * N_ + n] = p;
                    g_Vt[((long)(bb * H_ + h) * DH + d + 1) * N_ + n] = q;
                }
            }
        }
    }
}

// ===========================================================================
// Kernel 2: sim + exp + rowsum.  Writes p = exp(S*SCALE) UNNORMALIZED to attn
// (row-major, same as before) and 1/rowsum to g_RS.  K frag buffer swizzled.
// ===========================================================================
#define SIM_SMEM ((16384 + 2*4096 + 128) * 4)   // 98816 B

__global__ __launch_bounds__(256) void sim_tc(float* __restrict__ attn)
{
    extern __shared__ uint32_t sm[];
    uint32_t* Qs = sm;              // [qm4][ma2][ks16][lane32][4]
    uint32_t* Kb = sm + 16384;      // 2 x [wn2][na8][ks4][lane32][2] (swizzled)
    float* rowsumS = (float*)(sm + 24576);   // [128]

    const int tid = threadIdx.x, lane = tid & 31, wid = tid >> 5;
    const int wm = wid >> 1, wn = wid & 1;
    const int bh = blockIdx.y, rb = blockIdx.x;
    const float* Qg = g_Q2 + ((long)bh * N_ + rb * 128) * DQ2;
    const float* Kg = g_K2 + (long)bh * N_ * DQ2;
    float* outp = attn + (long)bh * N_ * N_ + (long)rb * 128 * N_;

    for (int e = tid; e < 4096; e += 256) {
        int l = e & 31, ks = (e >> 5) & 15, ma = (e >> 9) & 1, qm = e >> 10;
        int r = qm * 32 + ma * 16 + (l >> 2), c = ks * 8 + (l & 3);
        uint4 v;
        v.x = __float_as_uint(Qg[(long)r * DQ2 + c]);
        v.y = __float_as_uint(Qg[(long)(r + 8) * DQ2 + c]);
        v.z = __float_as_uint(Qg[(long)r * DQ2 + c + 4]);
        v.w = __float_as_uint(Qg[(long)(r + 8) * DQ2 + c + 4]);
        *(uint4*)&Qs[e * 4] = v;
    }
    if (tid < 128) rowsumS[tid] = 0.f;

    float4 tmp[4];
    auto loadK = [&](int it) {
        int ct = it >> 2, kc = it & 3;
        const float* src = Kg + (long)(ct * 128) * DQ2 + kc * 32;
        #pragma unroll
        for (int q = 0; q < 4; q++) {
            int e = tid + q * 256;
            int col = e >> 3, kg = e & 7;
            tmp[q] = *(const float4*)(src + (long)col * DQ2 + kg * 4);
        }
    };
    auto storeK = [&](int buf) {
        uint32_t* Bb = Kb + buf * 4096;
        #pragma unroll
        for (int q = 0; q < 4; q++) {
            int e = tid + q * 256;
            int col = e >> 3, kg = e & 7;
            int wn_ = col >> 6, na = (col >> 3) & 7;
            uint32_t vv[4] = { __float_as_uint(tmp[q].x), __float_as_uint(tmp[q].y),
                               __float_as_uint(tmp[q].z), __float_as_uint(tmp[q].w) };
            #pragma unroll
            for (int t = 0; t < 4; t++) {
                int k = kg * 4 + t;
                int l = ((col & 7) << 2) | (k & 3);
                int idx = ((((wn_ * 8 + na) * 4 + (k >> 3)) * 32) + l) * 2 + ((k >> 2) & 1);
                idx ^= ((k >> 3) & 3) << 1;            // bank swizzle
                Bb[idx] = vv[t];
            }
        }
    };

    float rs[2][2] = {};
    float acc[2][8][4];
    loadK(0); storeK(0);
    __syncthreads();

    for (int it = 0; it < 64; it++) {
        const int kc = it & 3, buf = it & 1;
        if (kc == 0) {
            #pragma unroll
            for (int i = 0; i < 2; i++)
                #pragma unroll
                for (int j = 0; j < 8; j++)
                    #pragma unroll
                    for (int t = 0; t < 4; t++) acc[i][j][t] = 0.f;
        }
        if (it + 1 < 64) loadK(it + 1);

        const uint32_t* Bb = Kb + buf * 4096;
        #pragma unroll
        for (int ksl = 0; ksl < 4; ksl++) {
            int ksg = kc * 4 + ksl;
            uint32_t a[2][4], b[8][2];
            *(uint4*)a[0] = *(const uint4*)&Qs[(((wm * 2 + 0) * 16 + ksg) * 32 + lane) * 4];
            *(uint4*)a[1] = *(const uint4*)&Qs[(((wm * 2 + 1) * 16 + ksg) * 32 + lane) * 4];
            #pragma unroll
            for (int na = 0; na < 8; na++)
                *(uint2*)b[na] = *(const uint2*)&Bb[(((((wn * 8 + na) * 4 + ksl) * 32 + lane) * 2)
                                                    ^ ((ksl & 3) << 1))];
            #pragma unroll
            for (int ma = 0; ma < 2; ma++)
                #pragma unroll
                for (int na = 0; na < 8; na++)
                    mma8(acc[ma][na], a[ma], b[na]);
        }

        if (kc == 3) {
            int ct = it >> 2;
            #pragma unroll
            for (int ma = 0; ma < 2; ma++) {
                int row = wm * 32 + ma * 16 + (lane >> 2);
                #pragma unroll
                for (int na = 0; na < 8; na++) {
                    int col = ct * 128 + wn * 64 + na * 8 + (lane & 3) * 2;
                    float p0 = __expf(acc[ma][na][0] * SCALE);
                    float p1 = __expf(acc[ma][na][1] * SCALE);
                    float p2 = __expf(acc[ma][na][2] * SCALE);
                    float p3 = __expf(acc[ma][na][3] * SCALE);
                    rs[ma][0] += p0 + p1;
                    rs[ma][1] += p2 + p3;
                    *(float2*)&outp[(long)row * N_ + col]       = make_float2(p0, p1);
                    *(float2*)&outp[(long)(row + 8) * N_ + col] = make_float2(p2, p3);
                }
            }
        }
        if (it + 1 < 64) storeK(buf ^ 1);
        __syncthreads();
    }

    // per-row sums: shfl across the 4 lanes of each row, then smem atomics
    #pragma unroll
    for (int ma = 0; ma < 2; ma++)
        #pragma unroll
        for (int hf = 0; hf < 2; hf++) {
            float v = rs[ma][hf];
            v += __shfl_xor_sync(0xffffffffu, v, 1);
            v += __shfl_xor_sync(0xffffffffu, v, 2);
            if ((lane & 3) == 0)
                atomicAdd(&rowsumS[wm * 32 + ma * 16 + hf * 8 + (lane >> 2)], v);
        }
    __syncthreads();
    if (tid < 128)
        g_RS[bh * N_ + rb * 128 + tid] = 1.0f / rowsumS[tid];
}

// ===========================================================================
// Kernel 3: pv + normalize.  A-loader scales unnormalized p by 1/rowsum,
// writes normalized attn back (final output), feeds tf32 frags to MMA.
// XOR bank-swizzled frag buffers (R8).
// ===========================================================================
#define PV_SMEM ((2*4096 + 2*2048 + 128) * 4)   // 49664 B

__global__ __launch_bounds__(256) void pv_tc(float* __restrict__ attn)
{
    extern __shared__ uint32_t sm[];
    uint32_t* Ab = sm;            // 2 x [wm4][ma2][ks4][lane32][4] (swizzled)
    uint32_t* Bv = sm + 8192;     // 2 x [wn2][na4][ks4][lane32][2] (swizzled)
    float* sInv = (float*)(sm + 12288);   // [128]

    const int tid = threadIdx.x, lane = tid & 31, wid = tid >> 5;
    const int wm = wid >> 1, wn = wid & 1;
    const int bh = blockIdx.y, rb = blockIdx.x;
    float* Ag = attn + (long)bh * N_ * N_ + (long)rb * 128 * N_;
    const float* Vg = g_Vt + (long)bh * DH * N_;

    if (tid < 128) sInv[tid] = g_RS[bh * N_ + rb * 128 + tid];
    __syncthreads();

    float4 ta[4], tb[2];
    auto loadT = [&](int it) {
        #pragma unroll
        for (int q = 0; q < 4; q++) {
            int e = tid + q * 256;
            int row = e >> 3, kg = e & 7;
            float4 v = *(const float4*)(Ag + (long)row * N_ + it * 32 + kg * 4);
            float iv = sInv[row];
            v.x *= iv; v.y *= iv; v.z *= iv; v.w *= iv;
            *(float4*)(Ag + (long)row * N_ + it * 32 + kg * 4) = v;   // final attn
            ta[q] = v;
        }
        #pragma unroll
        for (int q = 0; q < 2; q++) {
            int e = tid + q * 256;
            int d = e >> 3, kg = e & 7;
            tb[q] = *(const float4*)(Vg + (long)d * N_ + it * 32 + kg * 4);
        }
    };
    auto storeT = [&](int buf) {
        uint32_t* A = Ab + buf * 4096;
        #pragma unroll
        for (int q = 0; q < 4; q++) {
            int e = tid + q * 256;
            int row = e >> 3, kg = e & 7;
            int wm_ = row >> 5, ma = (row >> 4) & 1, rr = row & 15;
            float f[4] = { ta[q].x, ta[q].y, ta[q].z, ta[q].w };
            #pragma unroll
            for (int t = 0; t < 4; t++) {
                int k = kg * 4 + t;
                int ks = k >> 3;
                int j = ((k >> 2) & 1) * 2 + (rr >> 3);
                int l = (((rr & 7) << 2) | (k & 3)) ^ (ks & 3);   // bank swizzle
                A[((((wm_ * 2 + ma) * 4 + ks) * 32) + l) * 4 + j] =
                    __float_as_uint(tf32r(f[t]));
            }
        }
        uint32_t* Bt = Bv + buf * 2048;
        #pragma unroll
        for (int q = 0; q < 2; q++) {
            int e = tid + q * 256;
            int d = e >> 3, kg = e & 7;
            int wn_ = d >> 5, na = (d >> 3) & 3;
            float f[4] = { tb[q].x, tb[q].y, tb[q].z, tb[q].w };
            #pragma unroll
            for (int t = 0; t < 4; t++) {
                int k = kg * 4 + t;
                int l = ((d & 7) << 2) | (k & 3);
                int idx = ((((wn_ * 4 + na) * 4 + (k >> 3)) * 32) + l) * 2 + ((k >> 2) & 1);
                idx ^= ((k >> 3) & 3) << 1;                        // bank swizzle
                Bt[idx] = __float_as_uint(f[t]);
            }
        }
    };

    float acc[2][4][4] = {};
    loadT(0); storeT(0);
    __syncthreads();

    for (int it = 0; it < 64; it++) {
        const int buf = it & 1;
        if (it + 1 < 64) loadT(it + 1);

        const uint32_t* A = Ab + buf * 4096;
        const uint32_t* Bt = Bv + buf * 2048;
        #pragma unroll
        for (int ks = 0; ks < 4; ks++) {
            const int lsw = lane ^ (ks & 3);
            uint32_t a[2][4], b[4][2];
            *(uint4*)a[0] = *(const uint4*)&A[(((wm * 2 + 0) * 4 + ks) * 32 + lsw) * 4];
            *(uint4*)a[1] = *(const uint4*)&A[(((wm * 2 + 1) * 4 + ks) * 32 + lsw) * 4];
            #pragma unroll
            for (int na = 0; na < 4; na++)
                *(uint2*)b[na] = *(const uint2*)&Bt[(((((wn * 4 + na) * 4 + ks) * 32 + lane) * 2)
                                                    ^ ((ks & 3) << 1))];
            #pragma unroll
            for (int ma = 0; ma < 2; ma++)
                #pragma unroll
                for (int na = 0; na < 4; na++)
                    mma8(acc[ma][na], a[ma], b[na]);
        }
        if (it + 1 < 64) storeT(buf ^ 1);
        __syncthreads();
    }

    const int b = bh >> 3, h = bh & 7;
    float* oh = g_OH + ((long)b * N_ + rb * 128) * D_ + h * DH;
    #pragma unroll
    for (int ma = 0; ma < 2; ma++) {
        int row = wm * 32 + ma * 16 + (lane >> 2);
        #pragma unroll
        for (int na = 0; na < 4; na++) {
            int col = wn * 32 + na * 8 + (lane & 3) * 2;
            *(float2*)&oh[(long)row * D_ + col] =
                make_float2(acc[ma][na][0], acc[ma][na][1]);
            *(float2*)&oh[(long)(row + 8) * D_ + col] =
                make_float2(acc[ma][na][2], acc[ma][na][3]);
        }
    }
}

// ===========================================================================
// Kernel 4: Out = OutH @ Wo + bo via mma.sync tf32 (R5 verbatim)
// ===========================================================================
__global__ __launch_bounds__(256) void outproj_mma(
    const float* __restrict__ Wo, const float* __restrict__ bo,
    float* __restrict__ out)
{
    extern __shared__ float smf[];
    float* As = smf;
    float* Bs = smf + 2*128*APAD;

    const int tid = threadIdx.x, lane = tid & 31, wid = tid >> 5;
    const int wm = wid >> 1, wn = wid & 1;
    const int row0 = blockIdx.y * 128;
    const int col0 = blockIdx.x * 128;

    float4 ta[4]; float tb[16];
    auto loadA = [&](int k0) {
        #pragma unroll
        for (int q = 0; q < 4; q++) {
            int e = tid + q * 256;
            int r = e >> 3, kg = e & 7;
            ta[q] = *(const float4*)&g_OH[(long)(row0 + r) * D_ + k0 + kg * 4];
        }
    };
    auto loadB = [&](int k0) {
        #pragma unroll
        for (int j = 0; j < 16; j++) {
            int i = tid + j * 256;
            int k = i >> 7, n = i & 127;
            tb[j] = Wo[(long)(k0 + k) * D_ + col0 + n];
        }
    };
    auto stsA = [&](int buf) {
        float* Ab = As + buf * 128 * APAD;
        #pragma unroll
        for (int q = 0; q < 4; q++) {
            int e = tid + q * 256;
            int r = e >> 3, kg = e & 7;
            float4 v = ta[q];
            v.x = tf32r(v.x); v.y = tf32r(v.y); v.z = tf32r(v.z); v.w = tf32r(v.w);
            *(float4*)&Ab[r * APAD + kg * 4] = v;
        }
    };
    auto stsB = [&](int buf) {
        float* Bb = Bs + buf * 32 * BPAD;
        #pragma unroll
        for (int j = 0; j < 16; j++) {
            int i = tid + j * 256;
            int k = i >> 7, n = i & 127;
            Bb[k * BPAD + n] = tf32r(tb[j]);
        }
    };

    float acc[2][8][4] = {};
    loadA(0); loadB(0); stsA(0); stsB(0);
    __syncthreads();

    for (int c = 0; c < 16; c++) {
        if (c + 1 < 16) { loadA((c + 1) * 32); loadB((c + 1) * 32); }
        const int buf = c & 1;
        const float* Ab = As + buf * 128 * APAD;
        const float* Bb = Bs + buf * 32 * BPAD;

        #pragma unroll
        for (int ks = 0; ks < 4; ks++) {
            const int kk = ks * 8 + (lane & 3);
            uint32_t a[2][4], b[8][2];
            #pragma unroll
            for (int ma = 0; ma < 2; ma++) {
                int r = wm * 32 + ma * 16 + (lane >> 2);
                a[ma][0] = __float_as_uint(Ab[r * APAD + kk]);
                a[ma][1] = __float_as_uint(Ab[(r + 8) * APAD + kk]);
                a[ma][2] = __float_as_uint(Ab[r * APAD + kk + 4]);
                a[ma][3] = __float_as_uint(Ab[(r + 8) * APAD + kk + 4]);
            }
            #pragma unroll
            for (int na = 0; na < 8; na++) {
                int n = wn * 64 + na * 8 + (lane >> 2);
                b[na][0] = __float_as_uint(Bb[kk * BPAD + n]);
                b[na][1] = __float_as_uint(Bb[(kk + 4) * BPAD + n]);
            }
            #pragma unroll
            for (int ma = 0; ma < 2; ma++)
                #pragma unroll
                for (int na = 0; na < 8; na++)
                    mma8(acc[ma][na], a[ma], b[na]);
        }
        __syncthreads();
        if (c + 1 < 16) { stsA(buf ^ 1); stsB(buf ^ 1); }
        __syncthreads();
    }

    #pragma unroll
    for (int ma = 0; ma < 2; ma++) {
        #pragma unroll
        for (int half = 0; half < 2; half++) {
            int r = row0 + wm * 32 + ma * 16 + half * 8 + (lane >> 2);
            #pragma unroll
            for (int na = 0; na < 8; na++) {
                int cgl = col0 + wn * 64 + na * 8 + (lane & 3) * 2;
                float2 bias = *(const float2*)&bo[cgl];
                *(float2*)&out[(long)r * D_ + cgl] =
                    make_float2(acc[ma][na][half * 2 + 0] + bias.x,
                                acc[ma][na][half * 2 + 1] + bias.y);
            }
        }
    }
}

// ===========================================================================
extern "C" void kernel_launch(void* const* d_in, const int* in_sizes, int n_in,
                              void* d_out, int out_size)
{
    (void)in_sizes; (void)n_in; (void)out_size;
    const float* x   = (const float*)d_in[0];
    const float* met = (const float*)d_in[1];
    const float* yz  = (const float*)d_in[2];
    const float* Wq  = (const float*)d_in[3];
    const float* Wk  = (const float*)d_in[4];
    const float* Wv  = (const float*)d_in[5];
    const float* Wo  = (const float*)d_in[6];
    const float* bo  = (const float*)d_in[7];

    float* out  = (float*)d_out;                       // (4, 2048, 512)
    float* attn = out + (long)B_ * N_ * D_;            // (32, 2048, 2048)

    static int configured = 0;
    if (!configured) {
        cudaFuncSetAttribute(proj_mma,    cudaFuncAttributeMaxDynamicSharedMemorySize, PROJ_SMEM);
        cudaFuncSetAttribute(sim_tc,      cudaFuncAttributeMaxDynamicSharedMemorySize, SIM_SMEM);
        cudaFuncSetAttribute(pv_tc,       cudaFuncAttributeMaxDynamicSharedMemorySize, PV_SMEM);
        cudaFuncSetAttribute(outproj_mma, cudaFuncAttributeMaxDynamicSharedMemorySize, PROJ_SMEM);
        configured = 1;
    }

    proj_mma   <<<dim3(4, 64, 5), 256, PROJ_SMEM>>>(x, met, yz, Wq, Wk, Wv);
    sim_tc     <<<dim3(16, 32), 256, SIM_SMEM>>>(attn);
    pv_tc      <<<dim3(16, 32), 256, PV_SMEM>>>(attn);
    outproj_mma<<<dim3(4, 64), 256, PROJ_SMEM>>>(Wo, bo, out);
}

// round 10
// speedup vs baseline: 1.3461x; 1.3461x over previous
#include <cuda_runtime.h>
#include <cuda_fp16.h>
#include <math.h>
#include <cstdint>

#define B_   4
#define N_   2048
#define D_   512
#define H_   8
#define DH   64
#define DQ2  128          // concatenated head dim: [q | q_met]
#define BHn  (B_*H_)      // 32
#define ROWS (B_*N_)      // 8192
#define SCALE 0.125f      // 64^-0.5

// Scratch (device globals — no allocations allowed)
__device__ __half g_Q2h[BHn * N_ * DQ2];  // 16 MB [(bh), n, 128]
__device__ __half g_K2h[BHn * N_ * DQ2];  // 16 MB
__device__ __half g_Vth[BHn * DH * N_];   //  8 MB [(bh), d, n]
__device__ float  g_OH [ROWS * D_];       // 16 MB (b, n, h*64+d)

// ===========================================================================
// helpers
// ===========================================================================
__device__ __forceinline__ float tf32r(float x) {
    uint32_t u = __float_as_uint(x);
    asm("cvt.rn.tf32.f32 %0, %1;" : "=r"(u) : "r"(u));
    return __uint_as_float(u);
}
__device__ __forceinline__ uint32_t h2u(float a, float b) {
    __half2 h = __floats2half2_rn(a, b);
    return *(uint32_t*)&h;
}
__device__ __forceinline__ void mma8(float c[4], const uint32_t a[4], const uint32_t b[2]) {
    asm volatile(
        "mma.sync.aligned.m16n8k8.row.col.f32.tf32.tf32.f32 "
        "{%0,%1,%2,%3}, {%4,%5,%6,%7}, {%8,%9}, {%0,%1,%2,%3};"
        : "+f"(c[0]), "+f"(c[1]), "+f"(c[2]), "+f"(c[3])
        : "r"(a[0]), "r"(a[1]), "r"(a[2]), "r"(a[3]), "r"(b[0]), "r"(b[1]));
}
__device__ __forceinline__ void mma16(float c[4], const uint32_t a[4], const uint32_t b[2]) {
    asm volatile(
        "mma.sync.aligned.m16n8k16.row.col.f32.f16.f16.f32 "
        "{%0,%1,%2,%3}, {%4,%5,%6,%7}, {%8,%9}, {%0,%1,%2,%3};"
        : "+f"(c[0]), "+f"(c[1]), "+f"(c[2]), "+f"(c[3])
        : "r"(a[0]), "r"(a[1]), "r"(a[2]), "r"(a[3]), "r"(b[0]), "r"(b[1]));
}

// ===========================================================================
// Kernel 1: proj via mma.sync tf32; epilogue writes fp16 head-split tensors.
// ===========================================================================
#define APAD 44
#define BPAD 136
#define PROJ_SMEM ((2*128*APAD + 2*32*BPAD) * 4)   // 79872 B

__global__ __launch_bounds__(256) void proj_mma(
    const float* __restrict__ x, const float* __restrict__ met,
    const float* __restrict__ yz, const float* __restrict__ Wq,
    const float* __restrict__ Wk, const float* __restrict__ Wv)
{
    extern __shared__ float smf[];
    float* As = smf;                    // 2 x [128][APAD]
    float* Bs = smf + 2*128*APAD;       // 2 x [32][BPAD]

    const int mode = blockIdx.z;
    const float* A = (mode == 0) ? x : (mode == 1 || mode == 3) ? met : yz;
    const float* W = (mode < 2) ? Wq : (mode < 4) ? Wk : Wv;

    const int tid = threadIdx.x, lane = tid & 31, wid = tid >> 5;
    const int wm = wid >> 1, wn = wid & 1;
    const int row0 = blockIdx.y * 128;
    const int col0 = blockIdx.x * 128;

    float4 ta[4]; float tb[16];
    auto loadA = [&](int k0) {
        #pragma unroll
        for (int q = 0; q < 4; q++) {
            int e = tid + q * 256;
            int r = e >> 3, kg = e & 7;
            ta[q] = *(const float4*)&A[(long)(row0 + r) * D_ + k0 + kg * 4];
        }
    };
    auto loadB = [&](int k0) {
        #pragma unroll
        for (int j = 0; j < 16; j++) {
            int i = tid + j * 256;
            int k = i >> 7, n = i & 127;
            tb[j] = W[(long)(k0 + k) * D_ + col0 + n];
        }
    };
    auto stsA = [&](int buf) {
        float* Ab = As + buf * 128 * APAD;
        #pragma unroll
        for (int q = 0; q < 4; q++) {
            int e = tid + q * 256;
            int r = e >> 3, kg = e & 7;
            float4 v = ta[q];
            v.x = tf32r(v.x); v.y = tf32r(v.y); v.z = tf32r(v.z); v.w = tf32r(v.w);
            *(float4*)&Ab[r * APAD + kg * 4] = v;
        }
    };
    auto stsB = [&](int buf) {
        float* Bb = Bs + buf * 32 * BPAD;
        #pragma unroll
        for (int j = 0; j < 16; j++) {
            int i = tid + j * 256;
            int k = i >> 7, n = i & 127;
            Bb[k * BPAD + n] = tf32r(tb[j]);
        }
    };

    float acc[2][8][4] = {};
    loadA(0); loadB(0); stsA(0); stsB(0);
    __syncthreads();

    for (int c = 0; c < 16; c++) {
        if (c + 1 < 16) { loadA((c + 1) * 32); loadB((c + 1) * 32); }
        const int buf = c & 1;
        const float* Ab = As + buf * 128 * APAD;
        const float* Bb = Bs + buf * 32 * BPAD;

        #pragma unroll
        for (int ks = 0; ks < 4; ks++) {
            const int kk = ks * 8 + (lane & 3);
            uint32_t a[2][4], b[8][2];
            #pragma unroll
            for (int ma = 0; ma < 2; ma++) {
                int r = wm * 32 + ma * 16 + (lane >> 2);
                a[ma][0] = __float_as_uint(Ab[r * APAD + kk]);
                a[ma][1] = __float_as_uint(Ab[(r + 8) * APAD + kk]);
                a[ma][2] = __float_as_uint(Ab[r * APAD + kk + 4]);
                a[ma][3] = __float_as_uint(Ab[(r + 8) * APAD + kk + 4]);
            }
            #pragma unroll
            for (int na = 0; na < 8; na++) {
                int n = wn * 64 + na * 8 + (lane >> 2);
                b[na][0] = __float_as_uint(Bb[kk * BPAD + n]);
                b[na][1] = __float_as_uint(Bb[(kk + 4) * BPAD + n]);
            }
            #pragma unroll
            for (int ma = 0; ma < 2; ma++)
                #pragma unroll
                for (int na = 0; na < 8; na++)
                    mma8(acc[ma][na], a[ma], b[na]);
        }
        __syncthreads();
        if (c + 1 < 16) { stsA(buf ^ 1); stsB(buf ^ 1); }
        __syncthreads();
    }

    #pragma unroll
    for (int ma = 0; ma < 2; ma++) {
        #pragma unroll
        for (int half = 0; half < 2; half++) {
            int r = row0 + wm * 32 + ma * 16 + half * 8 + (lane >> 2);
            int bb = r >> 11, n = r & 2047;
            #pragma unroll
            for (int na = 0; na < 8; na++) {
                int cgl = col0 + wn * 64 + na * 8 + (lane & 3) * 2;
                int h = cgl >> 6, d = cgl & 63;
                float p = acc[ma][na][half * 2 + 0];
                float q = acc[ma][na][half * 2 + 1];
                long base = (long)(bb * H_ + h) * N_ + n;
                if (mode == 0)
                    *(__half2*)&g_Q2h[base * DQ2 + d] = __floats2half2_rn(p, q);
                else if (mode == 1)
                    *(__half2*)&g_Q2h[base * DQ2 + d + DH] = __floats2half2_rn(p, q);
                else if (mode == 2)
                    *(__half2*)&g_K2h[base * DQ2 + d] = __floats2half2_rn(p, q);
                else if (mode == 3)
                    *(__half2*)&g_K2h[base * DQ2 + d + DH] = __floats2half2_rn(p, q);
                else {
                    g_Vth[((long)(bb * H_ + h) * DH + d) * N_ + n] = __float2half_rn(p);
                    g_Vth[((long)(bb * H_ + h) * DH + d + 1) * N_ + n] = __float2half_rn(q);
                }
            }
        }
    }
}

// ===========================================================================
// Kernel 2: sim = (Q2 @ K2^T) * SCALE via mma.sync fp16 (m16n8k16).
// Q resident frags 32KB, K streamed in 32-k chunks (8KB x2, XOR-swizzled,
// conflict-free).  Epilogue writes fp32 attn, unchanged.
// ===========================================================================
#define SIM_SMEM ((8192 + 2*2048) * 4)   // 49152 B

__global__ __launch_bounds__(256) void sim_tc(float* __restrict__ attn)
{
    extern __shared__ uint32_t sm[];
    uint32_t* Qs = sm;              // [qm4][ma2][ks8][lane32][j4]
    uint32_t* Kb = sm + 8192;       // 2 x [wn2][na8][ks2][lane32][reg2] swizzled

    const int tid = threadIdx.x, lane = tid & 31, wid = tid >> 5;
    const int wm = wid >> 1, wn = wid & 1;
    const int bh = blockIdx.y, rb = blockIdx.x;
    const __half* Qg = g_Q2h + ((long)bh * N_ + rb * 128) * DQ2;
    const __half* Kg = g_K2h + (long)bh * N_ * DQ2;
    float* outp = attn + (long)bh * N_ * N_ + (long)rb * 128 * N_;

    // Q resident fragment fill (once)
    for (int e = tid; e < 8192; e += 256) {
        int j = e & 3, l = (e >> 2) & 31, ks = (e >> 7) & 7;
        int ma = (e >> 10) & 1, qm = (e >> 11) & 3;
        int r = qm * 32 + ma * 16 + (l >> 2) + (j & 1) * 8;
        int k = ks * 16 + (l & 3) * 2 + (j >> 1) * 8;
        Qs[e] = *(const uint32_t*)&Qg[(long)r * DQ2 + k];
    }

    uint4 tk[2];
    auto loadK = [&](int it) {
        int ct = it >> 2, kc = it & 3;
        const __half* src = Kg + (long)(ct * 128) * DQ2 + kc * 32;
        #pragma unroll
        for (int q = 0; q < 2; q++) {
            int e = tid + q * 256;
            int col = e >> 2, kq = e & 3;
            tk[q] = *(const uint4*)(src + (long)col * DQ2 + kq * 8);
        }
    };
    auto storeK = [&](int buf) {
        uint32_t* Bb = Kb + buf * 2048;
        #pragma unroll
        for (int q = 0; q < 2; q++) {
            int e = tid + q * 256;
            int col = e >> 2, kq = e & 3;
            int wn_ = col >> 6, na = (col >> 3) & 7;
            int cb2 = (col >> 2) & 1;
            uint32_t w4[4] = { tk[q].x, tk[q].y, tk[q].z, tk[q].w };
            #pragma unroll
            for (int w = 0; w < 4; w++) {
                int k2 = kq * 8 + w * 2;
                int ks = k2 >> 4, kk2 = k2 & 15;
                int lt = ((col & 7) << 2) | ((kk2 >> 1) & 3);
                int reg = kk2 >> 3;
                int idx = ((((wn_ * 8 + na) * 2 + ks) * 32) + lt) * 2 + reg;
                idx ^= (ks << 1) ^ (cb2 << 2);
                Bb[idx] = w4[w];
            }
        }
    };

    float acc[2][8][4];
    loadK(0); storeK(0);
    __syncthreads();

    const int ldxor = (((lane >> 4) & 1) << 2);
    for (int it = 0; it < 64; it++) {
        const int kc = it & 3, buf = it & 1;
        if (kc == 0) {
            #pragma unroll
            for (int i = 0; i < 2; i++)
                #pragma unroll
                for (int j = 0; j < 8; j++)
                    #pragma unroll
                    for (int t = 0; t < 4; t++) acc[i][j][t] = 0.f;
        }
        if (it + 1 < 64) loadK(it + 1);

        const uint32_t* Bb = Kb + buf * 2048;
        #pragma unroll
        for (int ks = 0; ks < 2; ks++) {
            int ksG = kc * 2 + ks;
            uint32_t a[2][4], b[8][2];
            *(uint4*)a[0] = *(const uint4*)&Qs[(((wm * 2 + 0) * 8 + ksG) * 32 + lane) * 4];
            *(uint4*)a[1] = *(const uint4*)&Qs[(((wm * 2 + 1) * 8 + ksG) * 32 + lane) * 4];
            #pragma unroll
            for (int na = 0; na < 8; na++) {
                int widx = ((((wn * 8 + na) * 2 + ks) * 32 + lane) * 2) ^ (ks << 1) ^ ldxor;
                *(uint2*)b[na] = *(const uint2*)&Bb[widx];
            }
            #pragma unroll
            for (int ma = 0; ma < 2; ma++)
                #pragma unroll
                for (int na = 0; na < 8; na++)
                    mma16(acc[ma][na], a[ma], b[na]);
        }

        if (kc == 3) {
            int ct = it >> 2;
            #pragma unroll
            for (int ma = 0; ma < 2; ma++) {
                int row = wm * 32 + ma * 16 + (lane >> 2);
                #pragma unroll
                for (int na = 0; na < 8; na++) {
                    int col = ct * 128 + wn * 64 + na * 8 + (lane & 3) * 2;
                    float2 lo = make_float2(acc[ma][na][0] * SCALE, acc[ma][na][1] * SCALE);
                    float2 hi = make_float2(acc[ma][na][2] * SCALE, acc[ma][na][3] * SCALE);
                    *(float2*)&outp[(long)row * N_ + col] = lo;
                    *(float2*)&outp[(long)(row + 8) * N_ + col] = hi;
                }
            }
        }
        if (it + 1 < 64) storeK(buf ^ 1);
        __syncthreads();
    }
}

// ===========================================================================
// Kernel 3: row softmax in place (R8 verbatim)
// ===========================================================================
__global__ __launch_bounds__(256) void softmax_kernel(float* __restrict__ attn)
{
    float* p = attn + (long)blockIdx.x * N_;
    const int tid = threadIdx.x;

    float4 v0 = ((const float4*)p)[tid];
    float4 v1 = ((const float4*)p)[tid + 256];

    float m = fmaxf(fmaxf(fmaxf(v0.x, v0.y), fmaxf(v0.z, v0.w)),
                    fmaxf(fmaxf(v1.x, v1.y), fmaxf(v1.z, v1.w)));
    #pragma unroll
    for (int o = 16; o > 0; o >>= 1) m = fmaxf(m, __shfl_xor_sync(0xffffffffu, m, o));

    __shared__ float redm[8];
    if ((tid & 31) == 0) redm[tid >> 5] = m;
    __syncthreads();
    float mm = redm[0];
    #pragma unroll
    for (int i = 1; i < 8; i++) mm = fmaxf(mm, redm[i]);

    float4 e0, e1;
    e0.x = __expf(v0.x - mm); e0.y = __expf(v0.y - mm);
    e0.z = __expf(v0.z - mm); e0.w = __expf(v0.w - mm);
    e1.x = __expf(v1.x - mm); e1.y = __expf(v1.y - mm);
    e1.z = __expf(v1.z - mm); e1.w = __expf(v1.w - mm);

    float s = (e0.x + e0.y) + (e0.z + e0.w) + (e1.x + e1.y) + (e1.z + e1.w);
    #pragma unroll
    for (int o = 16; o > 0; o >>= 1) s += __shfl_xor_sync(0xffffffffu, s, o);

    __shared__ float reds[8];
    if ((tid & 31) == 0) reds[tid >> 5] = s;
    __syncthreads();
    float ss = 0.f;
    #pragma unroll
    for (int i = 0; i < 8; i++) ss += reds[i];

    float inv = 1.0f / ss;
    e0.x *= inv; e0.y *= inv; e0.z *= inv; e0.w *= inv;
    e1.x *= inv; e1.y *= inv; e1.z *= inv; e1.w *= inv;
    ((float4*)p)[tid]       = e0;
    ((float4*)p)[tid + 256] = e1;
}

// ===========================================================================
// Kernel 4: OutH = attn @ V via mma.sync fp16 (m16n8k16).
// A converted fp32->half in loader; XOR-swizzled frag buffers.
// ===========================================================================
#define PV_SMEM ((2*2048 + 2*1024) * 4)   // 24576 B

__global__ __launch_bounds__(256) void pv_tc(const float* __restrict__ attn)
{
    extern __shared__ uint32_t sm[];
    uint32_t* Ab = sm;            // 2 x [wm4][ma2][ks2][lane32][j4] swizzled
    uint32_t* Bv = sm + 4096;     // 2 x [wn2][na4][ks2][lane32][reg2] swizzled

    const int tid = threadIdx.x, lane = tid & 31, wid = tid >> 5;
    const int wm = wid >> 1, wn = wid & 1;
    const int bh = blockIdx.y, rb = blockIdx.x;
    const float* Ag = attn + (long)bh * N_ * N_ + (long)rb * 128 * N_;
    const __half* Vg = g_Vth + (long)bh * DH * N_;

    float4 ta[4]; uint4 tv;
    auto loadT = [&](int it) {
        #pragma unroll
        for (int q = 0; q < 4; q++) {
            int e = tid + q * 256;
            int row = e >> 3, kg = e & 7;
            ta[q] = *(const float4*)(Ag + (long)row * N_ + it * 32 + kg * 4);
        }
        {
            int d = tid >> 2, kq = tid & 3;
            tv = *(const uint4*)(Vg + (long)d * N_ + it * 32 + kq * 8);
        }
    };
    auto storeT = [&](int buf) {
        uint32_t* A = Ab + buf * 2048;
        #pragma unroll
        for (int q = 0; q < 4; q++) {
            int e = tid + q * 256;
            int row = e >> 3, kg = e & 7;
            int wm_ = row >> 5, ma = (row >> 4) & 1, rr = row & 15;
            float f[4] = { ta[q].x, ta[q].y, ta[q].z, ta[q].w };
            #pragma unroll
            for (int w = 0; w < 2; w++) {
                int k2 = kg * 4 + w * 2;
                int ks = k2 >> 4, kk2 = k2 & 15;
                int lt = ((rr & 7) << 2) | ((kk2 >> 1) & 3);
                int j = (rr >> 3) | ((kk2 >> 3) << 1);
                int idx = (((((wm_ * 2 + ma) * 2 + ks) * 32) + lt) * 4 + j) ^ (ks << 2);
                A[idx] = h2u(f[w * 2], f[w * 2 + 1]);
            }
        }
        uint32_t* Bt = Bv + buf * 1024;
        {
            int d = tid >> 2, kq = tid & 3;
            int wn_ = d >> 5, na = (d >> 3) & 3;
            int cb2 = (d >> 2) & 1;
            uint32_t w4[4] = { tv.x, tv.y, tv.z, tv.w };
            #pragma unroll
            for (int w = 0; w < 4; w++) {
                int k2 = kq * 8 + w * 2;
                int ks = k2 >> 4, kk2 = k2 & 15;
                int lt = ((d & 7) << 2) | ((kk2 >> 1) & 3);
                int reg = kk2 >> 3;
                int idx = ((((wn_ * 4 + na) * 2 + ks) * 32) + lt) * 2 + reg;
                idx ^= (ks << 1) ^ (cb2 << 2);
                Bt[idx] = w4[w];
            }
        }
    };

    float acc[2][4][4] = {};
    loadT(0); storeT(0);
    __syncthreads();

    const int ldxor = (((lane >> 4) & 1) << 2);
    for (int it = 0; it < 64; it++) {
        const int buf = it & 1;
        if (it + 1 < 64) loadT(it + 1);

        const uint32_t* A = Ab + buf * 2048;
        const uint32_t* Bt = Bv + buf * 1024;
        #pragma unroll
        for (int ks = 0; ks < 2; ks++) {
            uint32_t a[2][4], b[4][2];
            *(uint4*)a[0] = *(const uint4*)&A[((((wm * 2 + 0) * 2 + ks) * 32 + lane) * 4) ^ (ks << 2)];
            *(uint4*)a[1] = *(const uint4*)&A[((((wm * 2 + 1) * 2 + ks) * 32 + lane) * 4) ^ (ks << 2)];
            #pragma unroll
            for (int na = 0; na < 4; na++) {
                int widx = ((((wn * 4 + na) * 2 + ks) * 32 + lane) * 2) ^ (ks << 1) ^ ldxor;
                *(uint2*)b[na] = *(const uint2*)&Bt[widx];
            }
            #pragma unroll
            for (int ma = 0; ma < 2; ma++)
                #pragma unroll
                for (int na = 0; na < 4; na++)
                    mma16(acc[ma][na], a[ma], b[na]);
        }
        if (it + 1 < 64) storeT(buf ^ 1);
        __syncthreads();
    }

    const int b = bh >> 3, h = bh & 7;
    float* oh = g_OH + ((long)b * N_ + rb * 128) * D_ + h * DH;
    #pragma unroll
    for (int ma = 0; ma < 2; ma++) {
        int row = wm * 32 + ma * 16 + (lane >> 2);
        #pragma unroll
        for (int na = 0; na < 4; na++) {
            int col = wn * 32 + na * 8 + (lane & 3) * 2;
            *(float2*)&oh[(long)row * D_ + col] =
                make_float2(acc[ma][na][0], acc[ma][na][1]);
            *(float2*)&oh[(long)(row + 8) * D_ + col] =
                make_float2(acc[ma][na][2], acc[ma][na][3]);
        }
    }
}

// ===========================================================================
// Kernel 5: Out = OutH @ Wo + bo via mma.sync tf32 (R8 verbatim)
// ===========================================================================
__global__ __launch_bounds__(256) void outproj_mma(
    const float* __restrict__ Wo, const float* __restrict__ bo,
    float* __restrict__ out)
{
    extern __shared__ float smf[];
    float* As = smf;
    float* Bs = smf + 2*128*APAD;

    const int tid = threadIdx.x, lane = tid & 31, wid = tid >> 5;
    const int wm = wid >> 1, wn = wid & 1;
    const int row0 = blockIdx.y * 128;
    const int col0 = blockIdx.x * 128;

    float4 ta[4]; float tb[16];
    auto loadA = [&](int k0) {
        #pragma unroll
        for (int q = 0; q < 4; q++) {
            int e = tid + q * 256;
            int r = e >> 3, kg = e & 7;
            ta[q] = *(const float4*)&g_OH[(long)(row0 + r) * D_ + k0 + kg * 4];
        }
    };
    auto loadB = [&](int k0) {
        #pragma unroll
        for (int j = 0; j < 16; j++) {
            int i = tid + j * 256;
            int k = i >> 7, n = i & 127;
            tb[j] = Wo[(long)(k0 + k) * D_ + col0 + n];
        }
    };
    auto stsA = [&](int buf) {
        float* Ab = As + buf * 128 * APAD;
        #pragma unroll
        for (int q = 0; q < 4; q++) {
            int e = tid + q * 256;
            int r = e >> 3, kg = e & 7;
            float4 v = ta[q];
            v.x = tf32r(v.x); v.y = tf32r(v.y); v.z = tf32r(v.z); v.w = tf32r(v.w);
            *(float4*)&Ab[r * APAD + kg * 4] = v;
        }
    };
    auto stsB = [&](int buf) {
        float* Bb = Bs + buf * 32 * BPAD;
        #pragma unroll
        for (int j = 0; j < 16; j++) {
            int i = tid + j * 256;
            int k = i >> 7, n = i & 127;
            Bb[k * BPAD + n] = tf32r(tb[j]);
        }
    };

    float acc[2][8][4] = {};
    loadA(0); loadB(0); stsA(0); stsB(0);
    __syncthreads();

    for (int c = 0; c < 16; c++) {
        if (c + 1 < 16) { loadA((c + 1) * 32); loadB((c + 1) * 32); }
        const int buf = c & 1;
        const float* Ab = As + buf * 128 * APAD;
        const float* Bb = Bs + buf * 32 * BPAD;

        #pragma unroll
        for (int ks = 0; ks < 4; ks++) {
            const int kk = ks * 8 + (lane & 3);
            uint32_t a[2][4], b[8][2];
            #pragma unroll
            for (int ma = 0; ma < 2; ma++) {
                int r = wm * 32 + ma * 16 + (lane >> 2);
                a[ma][0] = __float_as_uint(Ab[r * APAD + kk]);
                a[ma][1] = __float_as_uint(Ab[(r + 8) * APAD + kk]);
                a[ma][2] = __float_as_uint(Ab[r * APAD + kk + 4]);
                a[ma][3] = __float_as_uint(Ab[(r + 8) * APAD + kk + 4]);
            }
            #pragma unroll
            for (int na = 0; na < 8; na++) {
                int n = wn * 64 + na * 8 + (lane >> 2);
                b[na][0] = __float_as_uint(Bb[kk * BPAD + n]);
                b[na][1] = __float_as_uint(Bb[(kk + 4) * BPAD + n]);
            }
            #pragma unroll
            for (int ma = 0; ma < 2; ma++)
                #pragma unroll
                for (int na = 0; na < 8; na++)
                    mma8(acc[ma][na], a[ma], b[na]);
        }
        __syncthreads();
        if (c + 1 < 16) { stsA(buf ^ 1); stsB(buf ^ 1); }
        __syncthreads();
    }

    #pragma unroll
    for (int ma = 0; ma < 2; ma++) {
        #pragma unroll
        for (int half = 0; half < 2; half++) {
            int r = row0 + wm * 32 + ma * 16 + half * 8 + (lane >> 2);
            #pragma unroll
            for (int na = 0; na < 8; na++) {
                int cgl = col0 + wn * 64 + na * 8 + (lane & 3) * 2;
                float2 bias = *(const float2*)&bo[cgl];
                *(float2*)&out[(long)r * D_ + cgl] =
                    make_float2(acc[ma][na][half * 2 + 0] + bias.x,
                                acc[ma][na][half * 2 + 1] + bias.y);
            }
        }
    }
}

// ===========================================================================
extern "C" void kernel_launch(void* const* d_in, const int* in_sizes, int n_in,
                              void* d_out, int out_size)
{
    (void)in_sizes; (void)n_in; (void)out_size;
    const float* x   = (const float*)d_in[0];
    const float* met = (const float*)d_in[1];
    const float* yz  = (const float*)d_in[2];
    const float* Wq  = (const float*)d_in[3];
    const float* Wk  = (const float*)d_in[4];
    const float* Wv  = (const float*)d_in[5];
    const float* Wo  = (const float*)d_in[6];
    const float* bo  = (const float*)d_in[7];

    float* out  = (float*)d_out;                       // (4, 2048, 512)
    float* attn = out + (long)B_ * N_ * D_;            // (32, 2048, 2048)

    static int configured = 0;
    if (!configured) {
        cudaFuncSetAttribute(proj_mma,    cudaFuncAttributeMaxDynamicSharedMemorySize, PROJ_SMEM);
        cudaFuncSetAttribute(sim_tc,      cudaFuncAttributeMaxDynamicSharedMemorySize, SIM_SMEM);
        cudaFuncSetAttribute(pv_tc,       cudaFuncAttributeMaxDynamicSharedMemorySize, PV_SMEM);
        cudaFuncSetAttribute(outproj_mma, cudaFuncAttributeMaxDynamicSharedMemorySize, PROJ_SMEM);
        configured = 1;
    }

    proj_mma      <<<dim3(4, 64, 5), 256, PROJ_SMEM>>>(x, met, yz, Wq, Wk, Wv);
    sim_tc        <<<dim3(16, 32), 256, SIM_SMEM>>>(attn);
    softmax_kernel<<<BHn * N_, 256>>>(attn);
    pv_tc         <<<dim3(16, 32), 256, PV_SMEM>>>(attn);
    outproj_mma   <<<dim3(4, 64), 256, PROJ_SMEM>>>(Wo, bo, out);
}

// round 11
// speedup vs baseline: 1.3667x; 1.0153x over previous
#include <cuda_runtime.h>
#include <cuda_fp16.h>
#include <math.h>
#include <cstdint>

#define B_   4
#define N_   2048
#define D_   512
#define H_   8
#define DH   64
#define DQ2  128          // concatenated head dim: [q | q_met]
#define BHn  (B_*H_)      // 32
#define ROWS (B_*N_)      // 8192
#define SCALE 0.125f      // 64^-0.5

// Scratch (device globals — no allocations allowed)
__device__ __half g_Q2h[BHn * N_ * DQ2];  // 16 MB [(bh), n, 128]
__device__ __half g_K2h[BHn * N_ * DQ2];  // 16 MB
__device__ __half g_Vth[BHn * DH * N_];   //  8 MB [(bh), d, n]
__device__ float  g_OH [ROWS * D_];       // 16 MB (b, n, h*64+d)
__device__ float  g_RS [BHn * N_];        // 256 KB  1/rowsum

// ===========================================================================
// helpers
// ===========================================================================
__device__ __forceinline__ float tf32r(float x) {
    uint32_t u = __float_as_uint(x);
    asm("cvt.rn.tf32.f32 %0, %1;" : "=r"(u) : "r"(u));
    return __uint_as_float(u);
}
__device__ __forceinline__ uint32_t h2u(float a, float b) {
    __half2 h = __floats2half2_rn(a, b);
    return *(uint32_t*)&h;
}
__device__ __forceinline__ void mma8(float c[4], const uint32_t a[4], const uint32_t b[2]) {
    asm volatile(
        "mma.sync.aligned.m16n8k8.row.col.f32.tf32.tf32.f32 "
        "{%0,%1,%2,%3}, {%4,%5,%6,%7}, {%8,%9}, {%0,%1,%2,%3};"
        : "+f"(c[0]), "+f"(c[1]), "+f"(c[2]), "+f"(c[3])
        : "r"(a[0]), "r"(a[1]), "r"(a[2]), "r"(a[3]), "r"(b[0]), "r"(b[1]));
}
__device__ __forceinline__ void mma16(float c[4], const uint32_t a[4], const uint32_t b[2]) {
    asm volatile(
        "mma.sync.aligned.m16n8k16.row.col.f32.f16.f16.f32 "
        "{%0,%1,%2,%3}, {%4,%5,%6,%7}, {%8,%9}, {%0,%1,%2,%3};"
        : "+f"(c[0]), "+f"(c[1]), "+f"(c[2]), "+f"(c[3])
        : "r"(a[0]), "r"(a[1]), "r"(a[2]), "r"(a[3]), "r"(b[0]), "r"(b[1]));
}

// ===========================================================================
// Kernel 1: proj via mma.sync tf32; epilogue writes fp16 head-split tensors.
// (R10 verbatim)
// ===========================================================================
#define APAD 44
#define BPAD 136
#define PROJ_SMEM ((2*128*APAD + 2*32*BPAD) * 4)   // 79872 B

__global__ __launch_bounds__(256) void proj_mma(
    const float* __restrict__ x, const float* __restrict__ met,
    const float* __restrict__ yz, const float* __restrict__ Wq,
    const float* __restrict__ Wk, const float* __restrict__ Wv)
{
    extern __shared__ float smf[];
    float* As = smf;                    // 2 x [128][APAD]
    float* Bs = smf + 2*128*APAD;       // 2 x [32][BPAD]

    const int mode = blockIdx.z;
    const float* A = (mode == 0) ? x : (mode == 1 || mode == 3) ? met : yz;
    const float* W = (mode < 2) ? Wq : (mode < 4) ? Wk : Wv;

    const int tid = threadIdx.x, lane = tid & 31, wid = tid >> 5;
    const int wm = wid >> 1, wn = wid & 1;
    const int row0 = blockIdx.y * 128;
    const int col0 = blockIdx.x * 128;

    float4 ta[4]; float tb[16];
    auto loadA = [&](int k0) {
        #pragma unroll
        for (int q = 0; q < 4; q++) {
            int e = tid + q * 256;
            int r = e >> 3, kg = e & 7;
            ta[q] = *(const float4*)&A[(long)(row0 + r) * D_ + k0 + kg * 4];
        }
    };
    auto loadB = [&](int k0) {
        #pragma unroll
        for (int j = 0; j < 16; j++) {
            int i = tid + j * 256;
            int k = i >> 7, n = i & 127;
            tb[j] = W[(long)(k0 + k) * D_ + col0 + n];
        }
    };
    auto stsA = [&](int buf) {
        float* Ab = As + buf * 128 * APAD;
        #pragma unroll
        for (int q = 0; q < 4; q++) {
            int e = tid + q * 256;
            int r = e >> 3, kg = e & 7;
            float4 v = ta[q];
            v.x = tf32r(v.x); v.y = tf32r(v.y); v.z = tf32r(v.z); v.w = tf32r(v.w);
            *(float4*)&Ab[r * APAD + kg * 4] = v;
        }
    };
    auto stsB = [&](int buf) {
        float* Bb = Bs + buf * 32 * BPAD;
        #pragma unroll
        for (int j = 0; j < 16; j++) {
            int i = tid + j * 256;
            int k = i >> 7, n = i & 127;
            Bb[k * BPAD + n] = tf32r(tb[j]);
        }
    };

    float acc[2][8][4] = {};
    loadA(0); loadB(0); stsA(0); stsB(0);
    __syncthreads();

    for (int c = 0; c < 16; c++) {
        if (c + 1 < 16) { loadA((c + 1) * 32); loadB((c + 1) * 32); }
        const int buf = c & 1;
        const float* Ab = As + buf * 128 * APAD;
        const float* Bb = Bs + buf * 32 * BPAD;

        #pragma unroll
        for (int ks = 0; ks < 4; ks++) {
            const int kk = ks * 8 + (lane & 3);
            uint32_t a[2][4], b[8][2];
            #pragma unroll
            for (int ma = 0; ma < 2; ma++) {
                int r = wm * 32 + ma * 16 + (lane >> 2);
                a[ma][0] = __float_as_uint(Ab[r * APAD + kk]);
                a[ma][1] = __float_as_uint(Ab[(r + 8) * APAD + kk]);
                a[ma][2] = __float_as_uint(Ab[r * APAD + kk + 4]);
                a[ma][3] = __float_as_uint(Ab[(r + 8) * APAD + kk + 4]);
            }
            #pragma unroll
            for (int na = 0; na < 8; na++) {
                int n = wn * 64 + na * 8 + (lane >> 2);
                b[na][0] = __float_as_uint(Bb[kk * BPAD + n]);
                b[na][1] = __float_as_uint(Bb[(kk + 4) * BPAD + n]);
            }
            #pragma unroll
            for (int ma = 0; ma < 2; ma++)
                #pragma unroll
                for (int na = 0; na < 8; na++)
                    mma8(acc[ma][na], a[ma], b[na]);
        }
        __syncthreads();
        if (c + 1 < 16) { stsA(buf ^ 1); stsB(buf ^ 1); }
        __syncthreads();
    }

    #pragma unroll
    for (int ma = 0; ma < 2; ma++) {
        #pragma unroll
        for (int half = 0; half < 2; half++) {
            int r = row0 + wm * 32 + ma * 16 + half * 8 + (lane >> 2);
            int bb = r >> 11, n = r & 2047;
            #pragma unroll
            for (int na = 0; na < 8; na++) {
                int cgl = col0 + wn * 64 + na * 8 + (lane & 3) * 2;
                int h = cgl >> 6, d = cgl & 63;
                float p = acc[ma][na][half * 2 + 0];
                float q = acc[ma][na][half * 2 + 1];
                long base = (long)(bb * H_ + h) * N_ + n;
                if (mode == 0)
                    *(__half2*)&g_Q2h[base * DQ2 + d] = __floats2half2_rn(p, q);
                else if (mode == 1)
                    *(__half2*)&g_Q2h[base * DQ2 + d + DH] = __floats2half2_rn(p, q);
                else if (mode == 2)
                    *(__half2*)&g_K2h[base * DQ2 + d] = __floats2half2_rn(p, q);
                else if (mode == 3)
                    *(__half2*)&g_K2h[base * DQ2 + d + DH] = __floats2half2_rn(p, q);
                else {
                    g_Vth[((long)(bb * H_ + h) * DH + d) * N_ + n] = __float2half_rn(p);
                    g_Vth[((long)(bb * H_ + h) * DH + d + 1) * N_ + n] = __float2half_rn(q);
                }
            }
        }
    }
}

// ===========================================================================
// Kernel 2: sim STATS pass — fp16 sim compute, exp, per-row sums; NO attn
// writes.  Writes 1/rowsum to g_RS.
// ===========================================================================
#define STATS_SMEM ((8192 + 2*2048 + 128) * 4)   // 49664 B

__global__ __launch_bounds__(256) void sim_stats(void)
{
    extern __shared__ uint32_t sm[];
    uint32_t* Qs = sm;              // [qm4][ma2][ks8][lane32][j4]
    uint32_t* Kb = sm + 8192;       // 2 x swizzled K frag buf
    float* rowsumS = (float*)(sm + 12288);   // [128]

    const int tid = threadIdx.x, lane = tid & 31, wid = tid >> 5;
    const int wm = wid >> 1, wn = wid & 1;
    const int bh = blockIdx.y, rb = blockIdx.x;
    const __half* Qg = g_Q2h + ((long)bh * N_ + rb * 128) * DQ2;
    const __half* Kg = g_K2h + (long)bh * N_ * DQ2;

    for (int e = tid; e < 8192; e += 256) {
        int j = e & 3, l = (e >> 2) & 31, ks = (e >> 7) & 7;
        int ma = (e >> 10) & 1, qm = (e >> 11) & 3;
        int r = qm * 32 + ma * 16 + (l >> 2) + (j & 1) * 8;
        int k = ks * 16 + (l & 3) * 2 + (j >> 1) * 8;
        Qs[e] = *(const uint32_t*)&Qg[(long)r * DQ2 + k];
    }
    if (tid < 128) rowsumS[tid] = 0.f;

    uint4 tk[2];
    auto loadK = [&](int it) {
        int ct = it >> 2, kc = it & 3;
        const __half* src = Kg + (long)(ct * 128) * DQ2 + kc * 32;
        #pragma unroll
        for (int q = 0; q < 2; q++) {
            int e = tid + q * 256;
            int col = e >> 2, kq = e & 3;
            tk[q] = *(const uint4*)(src + (long)col * DQ2 + kq * 8);
        }
    };
    auto storeK = [&](int buf) {
        uint32_t* Bb = Kb + buf * 2048;
        #pragma unroll
        for (int q = 0; q < 2; q++) {
            int e = tid + q * 256;
            int col = e >> 2, kq = e & 3;
            int wn_ = col >> 6, na = (col >> 3) & 7;
            int cb2 = (col >> 2) & 1;
            uint32_t w4[4] = { tk[q].x, tk[q].y, tk[q].z, tk[q].w };
            #pragma unroll
            for (int w = 0; w < 4; w++) {
                int k2 = kq * 8 + w * 2;
                int ks = k2 >> 4, kk2 = k2 & 15;
                int lt = ((col & 7) << 2) | ((kk2 >> 1) & 3);
                int reg = kk2 >> 3;
                int idx = ((((wn_ * 8 + na) * 2 + ks) * 32) + lt) * 2 + reg;
                idx ^= (ks << 1) ^ (cb2 << 2);
                Bb[idx] = w4[w];
            }
        }
    };

    float rs[2][2] = {};
    float acc[2][8][4];
    loadK(0); storeK(0);
    __syncthreads();

    const int ldxor = (((lane >> 4) & 1) << 2);
    for (int it = 0; it < 64; it++) {
        const int kc = it & 3, buf = it & 1;
        if (kc == 0) {
            #pragma unroll
            for (int i = 0; i < 2; i++)
                #pragma unroll
                for (int j = 0; j < 8; j++)
                    #pragma unroll
                    for (int t = 0; t < 4; t++) acc[i][j][t] = 0.f;
        }
        if (it + 1 < 64) loadK(it + 1);

        const uint32_t* Bb = Kb + buf * 2048;
        #pragma unroll
        for (int ks = 0; ks < 2; ks++) {
            int ksG = kc * 2 + ks;
            uint32_t a[2][4], b[8][2];
            *(uint4*)a[0] = *(const uint4*)&Qs[(((wm * 2 + 0) * 8 + ksG) * 32 + lane) * 4];
            *(uint4*)a[1] = *(const uint4*)&Qs[(((wm * 2 + 1) * 8 + ksG) * 32 + lane) * 4];
            #pragma unroll
            for (int na = 0; na < 8; na++) {
                int widx = ((((wn * 8 + na) * 2 + ks) * 32 + lane) * 2) ^ (ks << 1) ^ ldxor;
                *(uint2*)b[na] = *(const uint2*)&Bb[widx];
            }
            #pragma unroll
            for (int ma = 0; ma < 2; ma++)
                #pragma unroll
                for (int na = 0; na < 8; na++)
                    mma16(acc[ma][na], a[ma], b[na]);
        }

        if (kc == 3) {
            #pragma unroll
            for (int ma = 0; ma < 2; ma++)
                #pragma unroll
                for (int na = 0; na < 8; na++) {
                    rs[ma][0] += __expf(acc[ma][na][0] * SCALE)
                                + __expf(acc[ma][na][1] * SCALE);
                    rs[ma][1] += __expf(acc[ma][na][2] * SCALE)
                                + __expf(acc[ma][na][3] * SCALE);
                }
        }
        if (it + 1 < 64) storeK(buf ^ 1);
        __syncthreads();
    }

    #pragma unroll
    for (int ma = 0; ma < 2; ma++)
        #pragma unroll
        for (int hf = 0; hf < 2; hf++) {
            float v = rs[ma][hf];
            v += __shfl_xor_sync(0xffffffffu, v, 1);
            v += __shfl_xor_sync(0xffffffffu, v, 2);
            if ((lane & 3) == 0)
                atomicAdd(&rowsumS[wm * 32 + ma * 16 + hf * 8 + (lane >> 2)], v);
        }
    __syncthreads();
    if (tid < 128)
        g_RS[bh * N_ + rb * 128 + tid] = 1.0f / rowsumS[tid];
}

// ===========================================================================
// Kernel 3: FUSED sim-recompute + normalized attn write + PV.
// Recomputes S, p = exp(S*SCALE)*inv (inv from g_RS), writes FINAL attn,
// and feeds p directly into PV mma (fp16 C-frag == A-frag layout; zero smem
// for the P operand).  V streams via 16KB/chunk double-buffered frag smem.
// Cross-wn OH partials reduced through smem at the end.
// ===========================================================================
#define FUS_SMEM ((8192 + 2*2048 + 2*4096 + 128) * 4)   // 82432 B

__global__ __launch_bounds__(256, 1) void sim_pv(float* __restrict__ attn)
{
    extern __shared__ uint32_t sm[];
    uint32_t* Qs = sm;              // 8192 words: Q frags
    uint32_t* Kb = sm + 8192;       // 2 x 2048: K frag dbuf
    uint32_t* Vb = sm + 12288;      // 2 x 4096: V frag dbuf (per 128-k chunk)
    float* sInv = (float*)(sm + 20480);   // [128]
    float* sRed = (float*)(sm + 12288);   // reduction reuses Vb (8192 floats)

    const int tid = threadIdx.x, lane = tid & 31, wid = tid >> 5;
    const int wm = wid >> 1, wn = wid & 1;
    const int bh = blockIdx.y, rb = blockIdx.x;
    const __half* Qg = g_Q2h + ((long)bh * N_ + rb * 128) * DQ2;
    const __half* Kg = g_K2h + (long)bh * N_ * DQ2;
    const __half* Vg = g_Vth + (long)bh * DH * N_;
    float* outp = attn + (long)bh * N_ * N_ + (long)rb * 128 * N_;

    // Q resident frags
    for (int e = tid; e < 8192; e += 256) {
        int j = e & 3, l = (e >> 2) & 31, ks = (e >> 7) & 7;
        int ma = (e >> 10) & 1, qm = (e >> 11) & 3;
        int r = qm * 32 + ma * 16 + (l >> 2) + (j & 1) * 8;
        int k = ks * 16 + (l & 3) * 2 + (j >> 1) * 8;
        Qs[e] = *(const uint32_t*)&Qg[(long)r * DQ2 + k];
    }
    if (tid < 128) sInv[tid] = g_RS[bh * N_ + rb * 128 + tid];

    uint4 tk[2]; uint4 tvv;
    auto loadK = [&](int it) {
        int ct = it >> 2, kc = it & 3;
        const __half* src = Kg + (long)(ct * 128) * DQ2 + kc * 32;
        #pragma unroll
        for (int q = 0; q < 2; q++) {
            int e = tid + q * 256;
            int col = e >> 2, kq = e & 3;
            tk[q] = *(const uint4*)(src + (long)col * DQ2 + kq * 8);
        }
    };
    auto storeK = [&](int buf) {
        uint32_t* Bb = Kb + buf * 2048;
        #pragma unroll
        for (int q = 0; q < 2; q++) {
            int e = tid + q * 256;
            int col = e >> 2, kq = e & 3;
            int wn_ = col >> 6, na = (col >> 3) & 7;
            int cb2 = (col >> 2) & 1;
            uint32_t w4[4] = { tk[q].x, tk[q].y, tk[q].z, tk[q].w };
            #pragma unroll
            for (int w = 0; w < 4; w++) {
                int k2 = kq * 8 + w * 2;
                int ks = k2 >> 4, kk2 = k2 & 15;
                int lt = ((col & 7) << 2) | ((kk2 >> 1) & 3);
                int reg = kk2 >> 3;
                int idx = ((((wn_ * 8 + na) * 2 + ks) * 32) + lt) * 2 + reg;
                idx ^= (ks << 1) ^ (cb2 << 2);
                Bb[idx] = w4[w];
            }
        }
    };
    // V: quarter kc of chunk ct (1 uint4/thread = 4KB)
    auto loadVq = [&](int ct, int kc) {
        int e = kc * 256 + tid;
        int d = e >> 4, kq = e & 15;
        tvv = *(const uint4*)(Vg + (long)d * N_ + ct * 128 + kq * 8);
    };
    auto storeVq = [&](int buf, int kc) {
        uint32_t* Bt = Vb + buf * 4096;
        int e = kc * 256 + tid;
        int d = e >> 4, kq = e & 15;
        int cb2 = (d >> 2) & 1;
        uint32_t w4[4] = { tvv.x, tvv.y, tvv.z, tvv.w };
        #pragma unroll
        for (int w = 0; w < 4; w++) {
            int k2 = kq * 8 + w * 2;
            int ks = k2 >> 4, kk2 = k2 & 15;
            int lt = ((d & 7) << 2) | ((kk2 >> 1) & 3);
            int reg = kk2 >> 3;
            int idx = (((d >> 3) * 8 + ks) * 32 + lt) * 2 + reg;
            idx ^= ((ks & 3) << 1) ^ (cb2 << 2);
            Bt[idx] = w4[w];
        }
    };

    // preload chunk 0 (K quarter 0 + full V chunk 0)
    loadK(0); storeK(0);
    #pragma unroll
    for (int kc = 0; kc < 4; kc++) { loadVq(0, kc); storeVq(0, kc); }
    __syncthreads();

    // per-warp inverse row sums (rows fixed for the whole kernel)
    float inv[2][2];
    {
        int r0 = wm * 32 + (lane >> 2);
        inv[0][0] = sInv[r0];      inv[0][1] = sInv[r0 + 8];
        inv[1][0] = sInv[r0 + 16]; inv[1][1] = sInv[r0 + 24];
    }

    float acc[2][8][4];
    float pacc[2][8][4] = {};     // PV accum: [ma][d-group][4]
    const int ldxor = (((lane >> 4) & 1) << 2);

    for (int it = 0; it < 64; it++) {
        const int kc = it & 3, buf = it & 1, ct = it >> 2;
        if (kc == 0) {
            #pragma unroll
            for (int i = 0; i < 2; i++)
                #pragma unroll
                for (int j = 0; j < 8; j++)
                    #pragma unroll
                    for (int t = 0; t < 4; t++) acc[i][j][t] = 0.f;
        }
        if (it + 1 < 64) loadK(it + 1);
        if (ct + 1 < 16) loadVq(ct + 1, kc);

        const uint32_t* Bb = Kb + buf * 2048;
        #pragma unroll
        for (int ks = 0; ks < 2; ks++) {
            int ksG = kc * 2 + ks;
            uint32_t a[2][4], b[8][2];
            *(uint4*)a[0] = *(const uint4*)&Qs[(((wm * 2 + 0) * 8 + ksG) * 32 + lane) * 4];
            *(uint4*)a[1] = *(const uint4*)&Qs[(((wm * 2 + 1) * 8 + ksG) * 32 + lane) * 4];
            #pragma unroll
            for (int na = 0; na < 8; na++) {
                int widx = ((((wn * 8 + na) * 2 + ks) * 32 + lane) * 2) ^ (ks << 1) ^ ldxor;
                *(uint2*)b[na] = *(const uint2*)&Bb[widx];
            }
            #pragma unroll
            for (int ma = 0; ma < 2; ma++)
                #pragma unroll
                for (int na = 0; na < 8; na++)
                    mma16(acc[ma][na], a[ma], b[na]);
        }

        if (kc == 3) {
            const int vbuf = ct & 1;
            const uint32_t* Bt = Vb + vbuf * 4096;
            #pragma unroll
            for (int ma = 0; ma < 2; ma++) {
                int row = wm * 32 + ma * 16 + (lane >> 2);
                // exp + normalize in place, write final attn
                #pragma unroll
                for (int na = 0; na < 8; na++) {
                    float p0 = __expf(acc[ma][na][0] * SCALE) * inv[ma][0];
                    float p1 = __expf(acc[ma][na][1] * SCALE) * inv[ma][0];
                    float p2 = __expf(acc[ma][na][2] * SCALE) * inv[ma][1];
                    float p3 = __expf(acc[ma][na][3] * SCALE) * inv[ma][1];
                    acc[ma][na][0] = p0; acc[ma][na][1] = p1;
                    acc[ma][na][2] = p2; acc[ma][na][3] = p3;
                    int col = ct * 128 + wn * 64 + na * 8 + (lane & 3) * 2;
                    *(float2*)&outp[(long)row * N_ + col]       = make_float2(p0, p1);
                    *(float2*)&outp[(long)(row + 8) * N_ + col] = make_float2(p2, p3);
                }
                // PV: C-frags ARE A-frags for fp16 mma
                #pragma unroll
                for (int g = 0; g < 4; g++) {
                    uint32_t a[4];
                    a[0] = h2u(acc[ma][2*g][0],   acc[ma][2*g][1]);
                    a[1] = h2u(acc[ma][2*g][2],   acc[ma][2*g][3]);
                    a[2] = h2u(acc[ma][2*g+1][0], acc[ma][2*g+1][1]);
                    a[3] = h2u(acc[ma][2*g+1][2], acc[ma][2*g+1][3]);
                    const int ksg = wn * 4 + g;
                    #pragma unroll
                    for (int nd = 0; nd < 8; nd++) {
                        uint32_t b[2];
                        int widx = (((nd * 8 + ksg) * 32 + lane) * 2)
                                   ^ ((ksg & 3) << 1) ^ ldxor;
                        *(uint2*)b = *(const uint2*)&Bt[widx];
                        mma16(pacc[ma][nd], a, b);
                    }
                }
            }
        }
        if (it + 1 < 64) storeK(buf ^ 1);
        if (ct + 1 < 16) storeVq((ct + 1) & 1, kc);
        __syncthreads();
    }

    // cross-wn reduction of OH partials through smem (reuses Vb area)
    if (wn == 0) {
        #pragma unroll
        for (int ma = 0; ma < 2; ma++) {
            int row = wm * 32 + ma * 16 + (lane >> 2);
            #pragma unroll
            for (int nd = 0; nd < 8; nd++) {
                int col = nd * 8 + (lane & 3) * 2;
                *(float2*)&sRed[row * 64 + col] =
                    make_float2(pacc[ma][nd][0], pacc[ma][nd][1]);
                *(float2*)&sRed[(row + 8) * 64 + col] =
                    make_float2(pacc[ma][nd][2], pacc[ma][nd][3]);
            }
        }
    }
    __syncthreads();
    if (wn == 1) {
        #pragma unroll
        for (int ma = 0; ma < 2; ma++) {
            int row = wm * 32 + ma * 16 + (lane >> 2);
            #pragma unroll
            for (int nd = 0; nd < 8; nd++) {
                int col = nd * 8 + (lane & 3) * 2;
                float2 v0 = *(float2*)&sRed[row * 64 + col];
                float2 v1 = *(float2*)&sRed[(row + 8) * 64 + col];
                v0.x += pacc[ma][nd][0]; v0.y += pacc[ma][nd][1];
                v1.x += pacc[ma][nd][2]; v1.y += pacc[ma][nd][3];
                *(float2*)&sRed[row * 64 + col] = v0;
                *(float2*)&sRed[(row + 8) * 64 + col] = v1;
            }
        }
    }
    __syncthreads();
    const int b = bh >> 3, h = bh & 7;
    float* oh = g_OH + ((long)b * N_ + rb * 128) * D_ + h * DH;
    #pragma unroll
    for (int q = 0; q < 8; q++) {
        int e = tid + q * 256;
        int r = e >> 4, c4 = (e & 15) * 4;
        *(float4*)&oh[(long)r * D_ + c4] = *(float4*)&sRed[r * 64 + c4];
    }
}

// ===========================================================================
// Kernel 4: Out = OutH @ Wo + bo via mma.sync tf32 (R10 verbatim)
// ===========================================================================
__global__ __launch_bounds__(256) void outproj_mma(
    const float* __restrict__ Wo, const float* __restrict__ bo,
    float* __restrict__ out)
{
    extern __shared__ float smf[];
    float* As = smf;
    float* Bs = smf + 2*128*APAD;

    const int tid = threadIdx.x, lane = tid & 31, wid = tid >> 5;
    const int wm = wid >> 1, wn = wid & 1;
    const int row0 = blockIdx.y * 128;
    const int col0 = blockIdx.x * 128;

    float4 ta[4]; float tb[16];
    auto loadA = [&](int k0) {
        #pragma unroll
        for (int q = 0; q < 4; q++) {
            int e = tid + q * 256;
            int r = e >> 3, kg = e & 7;
            ta[q] = *(const float4*)&g_OH[(long)(row0 + r) * D_ + k0 + kg * 4];
        }
    };
    auto loadB = [&](int k0) {
        #pragma unroll
        for (int j = 0; j < 16; j++) {
            int i = tid + j * 256;
            int k = i >> 7, n = i & 127;
            tb[j] = Wo[(long)(k0 + k) * D_ + col0 + n];
        }
    };
    auto stsA = [&](int buf) {
        float* Ab = As + buf * 128 * APAD;
        #pragma unroll
        for (int q = 0; q < 4; q++) {
            int e = tid + q * 256;
            int r = e >> 3, kg = e & 7;
            float4 v = ta[q];
            v.x = tf32r(v.x); v.y = tf32r(v.y); v.z = tf32r(v.z); v.w = tf32r(v.w);
            *(float4*)&Ab[r * APAD + kg * 4] = v;
        }
    };
    auto stsB = [&](int buf) {
        float* Bb = Bs + buf * 32 * BPAD;
        #pragma unroll
        for (int j = 0; j < 16; j++) {
            int i = tid + j * 256;
            int k = i >> 7, n = i & 127;
            Bb[k * BPAD + n] = tf32r(tb[j]);
        }
    };

    float acc[2][8][4] = {};
    loadA(0); loadB(0); stsA(0); stsB(0);
    __syncthreads();

    for (int c = 0; c < 16; c++) {
        if (c + 1 < 16) { loadA((c + 1) * 32); loadB((c + 1) * 32); }
        const int buf = c & 1;
        const float* Ab = As + buf * 128 * APAD;
        const float* Bb = Bs + buf * 32 * BPAD;

        #pragma unroll
        for (int ks = 0; ks < 4; ks++) {
            const int kk = ks * 8 + (lane & 3);
            uint32_t a[2][4], b[8][2];
            #pragma unroll
            for (int ma = 0; ma < 2; ma++) {
                int r = wm * 32 + ma * 16 + (lane >> 2);
                a[ma][0] = __float_as_uint(Ab[r * APAD + kk]);
                a[ma][1] = __float_as_uint(Ab[(r + 8) * APAD + kk]);
                a[ma][2] = __float_as_uint(Ab[r * APAD + kk + 4]);
                a[ma][3] = __float_as_uint(Ab[(r + 8) * APAD + kk + 4]);
            }
            #pragma unroll
            for (int na = 0; na < 8; na++) {
                int n = wn * 64 + na * 8 + (lane >> 2);
                b[na][0] = __float_as_uint(Bb[kk * BPAD + n]);
                b[na][1] = __float_as_uint(Bb[(kk + 4) * BPAD + n]);
            }
            #pragma unroll
            for (int ma = 0; ma < 2; ma++)
                #pragma unroll
                for (int na = 0; na < 8; na++)
                    mma8(acc[ma][na], a[ma], b[na]);
        }
        __syncthreads();
        if (c + 1 < 16) { stsA(buf ^ 1); stsB(buf ^ 1); }
        __syncthreads();
    }

    #pragma unroll
    for (int ma = 0; ma < 2; ma++) {
        #pragma unroll
        for (int half = 0; half < 2; half++) {
            int r = row0 + wm * 32 + ma * 16 + half * 8 + (lane >> 2);
            #pragma unroll
            for (int na = 0; na < 8; na++) {
                int cgl = col0 + wn * 64 + na * 8 + (lane & 3) * 2;
                float2 bias = *(const float2*)&bo[cgl];
                *(float2*)&out[(long)r * D_ + cgl] =
                    make_float2(acc[ma][na][half * 2 + 0] + bias.x,
                                acc[ma][na][half * 2 + 1] + bias.y);
            }
        }
    }
}

// ===========================================================================
extern "C" void kernel_launch(void* const* d_in, const int* in_sizes, int n_in,
                              void* d_out, int out_size)
{
    (void)in_sizes; (void)n_in; (void)out_size;
    const float* x   = (const float*)d_in[0];
    const float* met = (const float*)d_in[1];
    const float* yz  = (const float*)d_in[2];
    const float* Wq  = (const float*)d_in[3];
    const float* Wk  = (const float*)d_in[4];
    const float* Wv  = (const float*)d_in[5];
    const float* Wo  = (const float*)d_in[6];
    const float* bo  = (const float*)d_in[7];

    float* out  = (float*)d_out;                       // (4, 2048, 512)
    float* attn = out + (long)B_ * N_ * D_;            // (32, 2048, 2048)

    static int configured = 0;
    if (!configured) {
        cudaFuncSetAttribute(proj_mma,    cudaFuncAttributeMaxDynamicSharedMemorySize, PROJ_SMEM);
        cudaFuncSetAttribute(sim_stats,   cudaFuncAttributeMaxDynamicSharedMemorySize, STATS_SMEM);
        cudaFuncSetAttribute(sim_pv,      cudaFuncAttributeMaxDynamicSharedMemorySize, FUS_SMEM);
        cudaFuncSetAttribute(outproj_mma, cudaFuncAttributeMaxDynamicSharedMemorySize, PROJ_SMEM);
        configured = 1;
    }

    proj_mma   <<<dim3(4, 64, 5), 256, PROJ_SMEM>>>(x, met, yz, Wq, Wk, Wv);
    sim_stats  <<<dim3(16, 32), 256, STATS_SMEM>>>();
    sim_pv     <<<dim3(16, 32), 256, FUS_SMEM>>>(attn);
    outproj_mma<<<dim3(4, 64), 256, PROJ_SMEM>>>(Wo, bo, out);
}